// round 8
// baseline (speedup 1.0000x reference)
#include <cuda_runtime.h>
#include <cuda_fp16.h>
#include <math.h>
#include <stdint.h>

#define NN0 100000
#define NN1 150000
#define NN2 50000
#define NNZ00 1600000
#define NNZ12 200000
#define DD 128

#define NB0 98              // ceil(NN0/1024)
#define NB2 49              // ceil(NN2/1024)
#define NBT (NB0 + NB2)     // 147 <= 148 SMs: co-resident at occ 1
#define NAT (NBT * 1024)

// ---------------- device scratch (zero-initialized; tail restores zeros) ----------------
__device__ uint2 g_h0[(size_t)NN0 * 32];       // relu(x0) fp16
__device__ uint2 g_h1[(size_t)NN1 * 32];       // relu(x1) fp16
__device__ uint2 g_S0h[(size_t)NN0 * 32];      // S0 fp16
__device__ uint2 g_S2h[(size_t)NN2 * 32];      // S2 fp16
__device__ __half g_WT0hi[DD * DD];            // W0^T split planes [n][k]
__device__ __half g_WT0lo[DD * DD];
__device__ __half g_WT2hi[DD * DD];
__device__ __half g_WT2lo[DD * DD];
__device__ __align__(16) int g_rp0[NN0 + 4];
__device__ __align__(16) int g_fill0[NN0];
__device__ __align__(16) int g_rp2[NN2 + 4];
__device__ __align__(16) int g_fill2[NN2];
__device__ int  g_flagA[NBT];
__device__ int  g_bar1, g_bar2;
__device__ int2 g_e0[NNZ00];
__device__ int2 g_e2[NNZ12];

// ---------------- fused front: hist + conversions + W split + out_x1 + scan ----------------
__device__ __forceinline__ void grid_barrier(int* ctr) {
    __syncthreads();
    if (threadIdx.x == 0) {
        atomicAdd(ctr, 1);
        while (*(volatile int*)ctr < NBT) __nanosleep(40);
    }
    __syncthreads();
}

__global__ __launch_bounds__(1024, 1)
void front_kernel(const float* __restrict__ x0, const float* __restrict__ x1,
                  const int* __restrict__ r00, const int* __restrict__ r12,
                  const float* __restrict__ W0, const float* __restrict__ W12,
                  float* __restrict__ out_x1) {
    int tid  = threadIdx.x;
    int gtid = blockIdx.x * 1024 + tid;

    for (int i = gtid; i < NNZ00; i += NAT) atomicAdd(&g_fill0[r00[i]], 1);
    for (int i = gtid; i < NNZ12; i += NAT) atomicAdd(&g_fill2[r12[i]], 1);

    for (int i = gtid; i < DD * DD; i += NAT) {
        int r = i >> 7, c = i & 127;
        float w = W0[i];
        __half h = __float2half_rn(w);
        g_WT0hi[c * DD + r] = h;
        g_WT0lo[c * DD + r] = __float2half_rn(w - __half2float(h));
        w = W12[i];
        h = __float2half_rn(w);
        g_WT2hi[c * DD + r] = h;
        g_WT2lo[c * DD + r] = __float2half_rn(w - __half2float(h));
    }

    for (int i = gtid; i < NN0 * 32; i += NAT) {
        float4 v = ((const float4*)x0)[i];
        half2 p0 = __floats2half2_rn(fmaxf(v.x, 0.f), fmaxf(v.y, 0.f));
        half2 p1 = __floats2half2_rn(fmaxf(v.z, 0.f), fmaxf(v.w, 0.f));
        g_h0[i] = make_uint2(*(uint32_t*)&p0, *(uint32_t*)&p1);
    }
    for (int i = gtid; i < NN1 * 32; i += NAT) {
        float4 v = ((const float4*)x1)[i];
        v.x = fmaxf(v.x, 0.f); v.y = fmaxf(v.y, 0.f);
        v.z = fmaxf(v.z, 0.f); v.w = fmaxf(v.w, 0.f);
        ((float4*)out_x1)[i] = v;
        half2 p0 = __floats2half2_rn(v.x, v.y);
        half2 p1 = __floats2half2_rn(v.z, v.w);
        g_h1[i] = make_uint2(*(uint32_t*)&p0, *(uint32_t*)&p1);
    }

    grid_barrier(&g_bar1);

    __shared__ int wsum[32];
    __shared__ int s_off;
    int b = blockIdx.x;
    int* cntfill; int* rp; int R; int base0; int lastcb;
    if (b < NB0) { cntfill = g_fill0; rp = g_rp0; R = NN0; base0 = 0;   lastcb = NB0 - 1; }
    else         { cntfill = g_fill2; rp = g_rp2; R = NN2; base0 = NB0; lastcb = NB2 - 1; }
    int cb  = b - base0;
    int idx = cb * 1024 + tid;
    int c = (idx < R) ? cntfill[idx] : 0;

    int lane = tid & 31, w = tid >> 5;
    int inc = c;
    #pragma unroll
    for (int off = 1; off < 32; off <<= 1) {
        int v = __shfl_up_sync(0xffffffffu, inc, off);
        if (lane >= off) inc += v;
    }
    if (lane == 31) wsum[w] = inc;
    if (tid == 0) s_off = 0;
    __syncthreads();
    if (w == 0) {
        int v = wsum[lane];
        int winc = v;
        #pragma unroll
        for (int off = 1; off < 32; off <<= 1) {
            int u = __shfl_up_sync(0xffffffffu, winc, off);
            if (lane >= off) winc += u;
        }
        wsum[lane] = winc - v;
        if (lane == 31) g_flagA[b] = winc;
    }

    grid_barrier(&g_bar2);

    int local = 0;
    for (int j = base0 + tid; j < b; j += 1024) local += g_flagA[j];
    if (local) atomicAdd(&s_off, local);
    __syncthreads();
    int off = s_off;

    if (idx < R) {
        int v = off + wsum[w] + inc - c;
        rp[idx]      = v;
        cntfill[idx] = v;
    }
    if (tid == 1023 && cb == lastcb) rp[R] = off + wsum[31] + inc;
}

// ---------------- CSR fill ----------------
__global__ void fill2_kernel(const int* __restrict__ r00, const int* __restrict__ c00,
                             const float* __restrict__ v00,
                             const int* __restrict__ r12, const int* __restrict__ c12,
                             const float* __restrict__ v12) {
    int i = blockIdx.x * blockDim.x + threadIdx.x;
    if (i < NNZ00) {
        int p = atomicAdd(&g_fill0[r00[i]], 1);
        g_e0[p] = make_int2(c00[i], __float_as_int(v00[i]));
    } else {
        int j = i - NNZ00;
        if (j < NNZ12) {
            int p = atomicAdd(&g_fill2[r12[j]], 1);
            g_e2[p] = make_int2(c12[j], __float_as_int(v12[j]));
        }
    }
}

// ---------------- SpMM: warp-per-row, fp16 gather, fp32 accum, fp16 store ----------------
__device__ __forceinline__ float4 h4f(uint2 q) {
    float2 f0 = __half22float2(*(half2*)&q.x);
    float2 f1 = __half22float2(*(half2*)&q.y);
    return make_float4(f0.x, f0.y, f1.x, f1.y);
}

__device__ __forceinline__ void spmm_row(const uint2* __restrict__ xh,
                                         const int* __restrict__ rp,
                                         const int2* __restrict__ ed,
                                         uint2* __restrict__ S, int row, int lane) {
    int s = rp[row], e = rp[row + 1];
    float4 acc = make_float4(0.f, 0.f, 0.f, 0.f);
    int i = s;
    for (; i + 4 <= e; i += 4) {
        int2 e0 = ed[i], e1 = ed[i + 1], e2 = ed[i + 2], e3 = ed[i + 3];
        float4 xa = h4f(xh[(size_t)e0.x * 32 + lane]);
        float4 xb = h4f(xh[(size_t)e1.x * 32 + lane]);
        float4 xc = h4f(xh[(size_t)e2.x * 32 + lane]);
        float4 xd = h4f(xh[(size_t)e3.x * 32 + lane]);
        float v0 = __int_as_float(e0.y), v1 = __int_as_float(e1.y);
        float v2 = __int_as_float(e2.y), v3 = __int_as_float(e3.y);
        acc.x += v0 * xa.x + v1 * xb.x + v2 * xc.x + v3 * xd.x;
        acc.y += v0 * xa.y + v1 * xb.y + v2 * xc.y + v3 * xd.y;
        acc.z += v0 * xa.z + v1 * xb.z + v2 * xc.z + v3 * xd.z;
        acc.w += v0 * xa.w + v1 * xb.w + v2 * xc.w + v3 * xd.w;
    }
    for (; i < e; i++) {
        int2 e0 = ed[i];
        float v0 = __int_as_float(e0.y);
        float4 xa = h4f(xh[(size_t)e0.x * 32 + lane]);
        acc.x += v0 * xa.x; acc.y += v0 * xa.y;
        acc.z += v0 * xa.z; acc.w += v0 * xa.w;
    }
    half2 p0 = __floats2half2_rn(acc.x, acc.y);
    half2 p1 = __floats2half2_rn(acc.z, acc.w);
    S[(size_t)row * 32 + lane] = make_uint2(*(uint32_t*)&p0, *(uint32_t*)&p1);
}

__global__ void spmm2_kernel() {
    int warp = (blockIdx.x * blockDim.x + threadIdx.x) >> 5;
    int lane = threadIdx.x & 31;
    if (warp < NN0)            spmm_row(g_h0, g_rp0, g_e0, g_S0h, warp, lane);
    else if (warp < NN0 + NN2) spmm_row(g_h1, g_rp2, g_e2, g_S2h, warp - NN0, lane);
}

// ---------------- persistent GEMM: resident W, double-buffered cp.async A ----------------
#define PADH 136
#define T0 ((NN0 + 63) / 64)      // 1563 tiles
#define T2 ((NN2 + 63) / 64)      // 782 tiles
#define PB0 198                   // persistent blocks for matrix 0
#define PB2 98                    // persistent blocks for matrix 2
#define PBT (PB0 + PB2)           // 296 = 2 per SM
#define A_BUF (64 * PADH)         // halves per A buffer
#define GSMEM ((2 * DD * PADH + 2 * A_BUF) * 2)   // bytes

__device__ __forceinline__ void mma_f16(float* d, const uint32_t* a, const uint32_t* b) {
    asm volatile(
        "mma.sync.aligned.m16n8k16.row.col.f32.f16.f16.f32 "
        "{%0,%1,%2,%3}, {%4,%5,%6,%7}, {%8,%9}, {%0,%1,%2,%3};\n"
        : "+f"(d[0]), "+f"(d[1]), "+f"(d[2]), "+f"(d[3])
        : "r"(a[0]), "r"(a[1]), "r"(a[2]), "r"(a[3]), "r"(b[0]), "r"(b[1]));
}

__device__ __forceinline__ void cp_async16(uint32_t dst_s, const void* src, int src_bytes) {
    asm volatile("cp.async.cg.shared.global [%0], [%1], 16, %2;"
                 :: "r"(dst_s), "l"(src), "r"(src_bytes));
}

__global__ __launch_bounds__(256, 2)
void gemm2_f16_relu_kernel(float* __restrict__ out_y0, float* __restrict__ out_y2) {
    const uint2* Sh; const __half* WThi; const __half* WTlo; float* out; int M, T, first, stride;
    if (blockIdx.x < PB0) {
        Sh = g_S0h; WThi = g_WT0hi; WTlo = g_WT0lo; out = out_y0; M = NN0;
        T = T0; first = blockIdx.x; stride = PB0;
    } else {
        Sh = g_S2h; WThi = g_WT2hi; WTlo = g_WT2lo; out = out_y2; M = NN2;
        T = T2; first = blockIdx.x - PB0; stride = PB2;
    }

    extern __shared__ __half hsm[];
    __half* sWhi = hsm;                       // [128][PADH]
    __half* sWlo = hsm + DD * PADH;           // [128][PADH]
    __half* sA0  = hsm + 2 * DD * PADH;       // two A buffers [64][PADH]
    int tid = threadIdx.x;

    // stage W planes once
    for (int idx = tid; idx < DD * 16; idx += 256) {
        int n = idx >> 4, kc = idx & 15;
        *(int4*)(sWhi + n * PADH + kc * 8) = ((const int4*)WThi)[idx];
        *(int4*)(sWlo + n * PADH + kc * 8) = ((const int4*)WTlo)[idx];
    }

    int lane = tid & 31, wid = tid >> 5;
    int g = lane >> 2, i4 = lane & 3;
    int mg = wid & 1, ng = wid >> 1;

    // A tile async loader: 1024 16B-chunks, 4 per thread
    uint32_t sA_base = (uint32_t)__cvta_generic_to_shared(sA0);
    int chunk_r[4], chunk_c[4];
    #pragma unroll
    for (int q = 0; q < 4; q++) {
        int idx = tid + q * 256;              // 0..1023
        chunk_r[q] = idx >> 4;                // row 0..63
        chunk_c[q] = idx & 15;                // 16B chunk in row
    }

    #define LOAD_TILE(buf, t) do {                                            \
        int m0_ = (t) * 64;                                                   \
        uint32_t dstb = sA_base + (buf) * (A_BUF * 2);                        \
        _Pragma("unroll")                                                     \
        for (int q = 0; q < 4; q++) {                                         \
            int gr = m0_ + chunk_r[q];                                        \
            uint32_t d = dstb + chunk_r[q] * (PADH * 2) + chunk_c[q] * 16;    \
            const char* s = (const char*)(Sh + (size_t)gr * 32) + chunk_c[q] * 16; \
            cp_async16(d, s, (gr < M) ? 16 : 0);                              \
        }                                                                     \
        asm volatile("cp.async.commit_group;");                               \
    } while (0)

    int t = first;
    if (t < T) LOAD_TILE(0, t);
    int buf = 0;

    for (; t < T; t += stride) {
        int tn = t + stride;
        if (tn < T) {
            LOAD_TILE(buf ^ 1, tn);
            asm volatile("cp.async.wait_group 1;");
        } else {
            asm volatile("cp.async.wait_group 0;");
        }
        __syncthreads();

        const uint32_t* sA32 = (const uint32_t*)(sA0 + buf * A_BUF);
        const uint32_t* sH32 = (const uint32_t*)sWhi;
        const uint32_t* sL32 = (const uint32_t*)sWlo;

        float acc[2][4][4];
        #pragma unroll
        for (int mt = 0; mt < 2; mt++)
            #pragma unroll
            for (int nt = 0; nt < 4; nt++)
                #pragma unroll
                for (int q = 0; q < 4; q++) acc[mt][nt][q] = 0.f;

        #pragma unroll
        for (int kk = 0; kk < 8; kk++) {
            int kw = kk * 8 + i4;
            uint32_t a[2][4], bh[4][2], bl[4][2];
            #pragma unroll
            for (int mt = 0; mt < 2; mt++) {
                int row = (mg * 32 + mt * 16 + g) * (PADH / 2);
                a[mt][0] = sA32[row + kw];
                a[mt][1] = sA32[row + 8 * (PADH / 2) + kw];
                a[mt][2] = sA32[row + kw + 4];
                a[mt][3] = sA32[row + 8 * (PADH / 2) + kw + 4];
            }
            #pragma unroll
            for (int nt = 0; nt < 4; nt++) {
                int n = (ng * 32 + nt * 8 + g) * (PADH / 2);
                bh[nt][0] = sH32[n + kw];
                bh[nt][1] = sH32[n + kw + 4];
                bl[nt][0] = sL32[n + kw];
                bl[nt][1] = sL32[n + kw + 4];
            }
            #pragma unroll
            for (int mt = 0; mt < 2; mt++)
                #pragma unroll
                for (int nt = 0; nt < 4; nt++) {
                    mma_f16(acc[mt][nt], a[mt], bl[nt]);
                    mma_f16(acc[mt][nt], a[mt], bh[nt]);
                }
        }

        int m0 = t * 64;
        #pragma unroll
        for (int mt = 0; mt < 2; mt++) {
            int r0 = m0 + mg * 32 + mt * 16 + g;
            #pragma unroll
            for (int nt = 0; nt < 4; nt++) {
                int c = ng * 32 + nt * 8 + i4 * 2;
                if (r0 < M) {
                    float2 v = make_float2(fmaxf(acc[mt][nt][0], 0.f),
                                           fmaxf(acc[mt][nt][1], 0.f));
                    *(float2*)(out + (size_t)r0 * DD + c) = v;
                }
                if (r0 + 8 < M) {
                    float2 v = make_float2(fmaxf(acc[mt][nt][2], 0.f),
                                           fmaxf(acc[mt][nt][3], 0.f));
                    *(float2*)(out + (size_t)(r0 + 8) * DD + c) = v;
                }
            }
        }
        __syncthreads();   // protect buf before it is overwritten next iter
        buf ^= 1;
    }
    #undef LOAD_TILE
}

// ---------------- tail: re-zero counters/flags/barriers ----------------
__global__ void tail_kernel() {
    int i = blockIdx.x * blockDim.x + threadIdx.x;
    if (i < NN0) g_fill0[i] = 0;
    else if (i < NN0 + NN2) g_fill2[i - NN0] = 0;
    else if (i < NN0 + NN2 + NBT) g_flagA[i - NN0 - NN2] = 0;
    else if (i == NN0 + NN2 + NBT)     g_bar1 = 0;
    else if (i == NN0 + NN2 + NBT + 1) g_bar2 = 0;
}

// ---------------- host launch ----------------
extern "C" void kernel_launch(void* const* d_in, const int* in_sizes, int n_in,
                              void* d_out, int out_size) {
    const float* x0  = (const float*)d_in[0];
    const float* x1  = (const float*)d_in[1];
    const int*   r00 = (const int*)  d_in[2];
    const int*   c00 = (const int*)  d_in[3];
    const float* v00 = (const float*)d_in[4];
    const int*   r12 = (const int*)  d_in[5];
    const int*   c12 = (const int*)  d_in[6];
    const float* v12 = (const float*)d_in[7];
    const float* W0  = (const float*)d_in[8];
    const float* W12 = (const float*)d_in[9];

    float* out    = (float*)d_out;
    float* out_y0 = out;
    float* out_x1 = out + (size_t)NN0 * DD;
    float* out_y2 = out + (size_t)(NN0 + NN1) * DD;

    front_kernel<<<NBT, 1024>>>(x0, x1, r00, r12, W0, W12, out_x1);        // #1
    fill2_kernel<<<(NNZ00 + NNZ12 + 255) / 256, 256>>>(r00, c00, v00,
                                                       r12, c12, v12);    // #2
    spmm2_kernel<<<((NN0 + NN2) * 32 + 255) / 256, 256>>>();               // #3
    cudaFuncSetAttribute(gemm2_f16_relu_kernel,
                         cudaFuncAttributeMaxDynamicSharedMemorySize, GSMEM);
    gemm2_f16_relu_kernel<<<PBT, 256, GSMEM>>>(out_y0, out_y2);            // #4 (profiled)
    tail_kernel<<<(NN0 + NN2 + NBT + 2 + 255) / 256, 256>>>();             // #5
}

// round 9
// speedup vs baseline: 1.1410x; 1.1410x over previous
#include <cuda_runtime.h>
#include <cuda_fp16.h>
#include <math.h>
#include <stdint.h>

#define NN0 100000
#define NN1 150000
#define NN2 50000
#define NNZ00 1600000
#define NNZ12 200000
#define DD 128

#define NB0 98              // ceil(NN0/1024)
#define NB2 49              // ceil(NN2/1024)
#define NBT (NB0 + NB2)     // 147 <= 148 SMs: co-resident at occ 1
#define NAT (NBT * 1024)

// ---------------- device scratch (zero-initialized; tail restores zeros) ----------------
__device__ uint2 g_h0[(size_t)NN0 * 32];       // relu(x0) fp16
__device__ uint2 g_h1[(size_t)NN1 * 32];       // relu(x1) fp16
__device__ uint2 g_S0h[(size_t)NN0 * 32];      // S0 fp16
__device__ uint2 g_S2h[(size_t)NN2 * 32];      // S2 fp16
__device__ __half g_WT0hi[DD * DD];            // W0^T split planes [n][k]
__device__ __half g_WT0lo[DD * DD];
__device__ __half g_WT2hi[DD * DD];
__device__ __half g_WT2lo[DD * DD];
__device__ __align__(16) int g_rp0[NN0 + 4];
__device__ __align__(16) int g_fill0[NN0];
__device__ __align__(16) int g_rp2[NN2 + 4];
__device__ __align__(16) int g_fill2[NN2];
__device__ int  g_flagA[NBT];
__device__ int  g_bar1, g_bar2;
__device__ int2 g_e0[NNZ00];
__device__ int2 g_e2[NNZ12];

// ---------------- fused front: hist + conversions + W split + out_x1 + scan ----------------
__device__ __forceinline__ void grid_barrier(int* ctr) {
    __syncthreads();
    if (threadIdx.x == 0) {
        atomicAdd(ctr, 1);
        while (*(volatile int*)ctr < NBT) __nanosleep(40);
    }
    __syncthreads();
}

__global__ __launch_bounds__(1024, 1)
void front_kernel(const float* __restrict__ x0, const float* __restrict__ x1,
                  const int* __restrict__ r00, const int* __restrict__ r12,
                  const float* __restrict__ W0, const float* __restrict__ W12,
                  float* __restrict__ out_x1) {
    int tid  = threadIdx.x;
    int gtid = blockIdx.x * 1024 + tid;

    for (int i = gtid; i < NNZ00; i += NAT) atomicAdd(&g_fill0[r00[i]], 1);
    for (int i = gtid; i < NNZ12; i += NAT) atomicAdd(&g_fill2[r12[i]], 1);

    for (int i = gtid; i < DD * DD; i += NAT) {
        int r = i >> 7, c = i & 127;
        float w = W0[i];
        __half h = __float2half_rn(w);
        g_WT0hi[c * DD + r] = h;
        g_WT0lo[c * DD + r] = __float2half_rn(w - __half2float(h));
        w = W12[i];
        h = __float2half_rn(w);
        g_WT2hi[c * DD + r] = h;
        g_WT2lo[c * DD + r] = __float2half_rn(w - __half2float(h));
    }

    for (int i = gtid; i < NN0 * 32; i += NAT) {
        float4 v = ((const float4*)x0)[i];
        half2 p0 = __floats2half2_rn(fmaxf(v.x, 0.f), fmaxf(v.y, 0.f));
        half2 p1 = __floats2half2_rn(fmaxf(v.z, 0.f), fmaxf(v.w, 0.f));
        g_h0[i] = make_uint2(*(uint32_t*)&p0, *(uint32_t*)&p1);
    }
    for (int i = gtid; i < NN1 * 32; i += NAT) {
        float4 v = ((const float4*)x1)[i];
        v.x = fmaxf(v.x, 0.f); v.y = fmaxf(v.y, 0.f);
        v.z = fmaxf(v.z, 0.f); v.w = fmaxf(v.w, 0.f);
        ((float4*)out_x1)[i] = v;
        half2 p0 = __floats2half2_rn(v.x, v.y);
        half2 p1 = __floats2half2_rn(v.z, v.w);
        g_h1[i] = make_uint2(*(uint32_t*)&p0, *(uint32_t*)&p1);
    }

    grid_barrier(&g_bar1);

    __shared__ int wsum[32];
    __shared__ int s_off;
    int b = blockIdx.x;
    int* cntfill; int* rp; int R; int base0; int lastcb;
    if (b < NB0) { cntfill = g_fill0; rp = g_rp0; R = NN0; base0 = 0;   lastcb = NB0 - 1; }
    else         { cntfill = g_fill2; rp = g_rp2; R = NN2; base0 = NB0; lastcb = NB2 - 1; }
    int cb  = b - base0;
    int idx = cb * 1024 + tid;
    int c = (idx < R) ? cntfill[idx] : 0;

    int lane = tid & 31, w = tid >> 5;
    int inc = c;
    #pragma unroll
    for (int off = 1; off < 32; off <<= 1) {
        int v = __shfl_up_sync(0xffffffffu, inc, off);
        if (lane >= off) inc += v;
    }
    if (lane == 31) wsum[w] = inc;
    if (tid == 0) s_off = 0;
    __syncthreads();
    if (w == 0) {
        int v = wsum[lane];
        int winc = v;
        #pragma unroll
        for (int off = 1; off < 32; off <<= 1) {
            int u = __shfl_up_sync(0xffffffffu, winc, off);
            if (lane >= off) winc += u;
        }
        wsum[lane] = winc - v;
        if (lane == 31) g_flagA[b] = winc;
    }

    grid_barrier(&g_bar2);

    int local = 0;
    for (int j = base0 + tid; j < b; j += 1024) local += g_flagA[j];
    if (local) atomicAdd(&s_off, local);
    __syncthreads();
    int off = s_off;

    if (idx < R) {
        int v = off + wsum[w] + inc - c;
        rp[idx]      = v;
        cntfill[idx] = v;
    }
    if (tid == 1023 && cb == lastcb) rp[R] = off + wsum[31] + inc;
}

// ---------------- CSR fill ----------------
__global__ void fill2_kernel(const int* __restrict__ r00, const int* __restrict__ c00,
                             const float* __restrict__ v00,
                             const int* __restrict__ r12, const int* __restrict__ c12,
                             const float* __restrict__ v12) {
    int i = blockIdx.x * blockDim.x + threadIdx.x;
    if (i < NNZ00) {
        int p = atomicAdd(&g_fill0[r00[i]], 1);
        g_e0[p] = make_int2(c00[i], __float_as_int(v00[i]));
    } else {
        int j = i - NNZ00;
        if (j < NNZ12) {
            int p = atomicAdd(&g_fill2[r12[j]], 1);
            g_e2[p] = make_int2(c12[j], __float_as_int(v12[j]));
        }
    }
}

// ---------------- SpMM: warp-per-row, fp16 gather, fp32 accum, fp16 store ----------------
__device__ __forceinline__ float4 h4f(uint2 q) {
    float2 f0 = __half22float2(*(half2*)&q.x);
    float2 f1 = __half22float2(*(half2*)&q.y);
    return make_float4(f0.x, f0.y, f1.x, f1.y);
}

__device__ __forceinline__ void spmm_row(const uint2* __restrict__ xh,
                                         const int* __restrict__ rp,
                                         const int2* __restrict__ ed,
                                         uint2* __restrict__ S, int row, int lane) {
    int s = rp[row], e = rp[row + 1];
    float4 acc = make_float4(0.f, 0.f, 0.f, 0.f);
    int i = s;
    for (; i + 4 <= e; i += 4) {
        int2 e0 = ed[i], e1 = ed[i + 1], e2 = ed[i + 2], e3 = ed[i + 3];
        float4 xa = h4f(xh[(size_t)e0.x * 32 + lane]);
        float4 xb = h4f(xh[(size_t)e1.x * 32 + lane]);
        float4 xc = h4f(xh[(size_t)e2.x * 32 + lane]);
        float4 xd = h4f(xh[(size_t)e3.x * 32 + lane]);
        float v0 = __int_as_float(e0.y), v1 = __int_as_float(e1.y);
        float v2 = __int_as_float(e2.y), v3 = __int_as_float(e3.y);
        acc.x += v0 * xa.x + v1 * xb.x + v2 * xc.x + v3 * xd.x;
        acc.y += v0 * xa.y + v1 * xb.y + v2 * xc.y + v3 * xd.y;
        acc.z += v0 * xa.z + v1 * xb.z + v2 * xc.z + v3 * xd.z;
        acc.w += v0 * xa.w + v1 * xb.w + v2 * xc.w + v3 * xd.w;
    }
    for (; i < e; i++) {
        int2 e0 = ed[i];
        float v0 = __int_as_float(e0.y);
        float4 xa = h4f(xh[(size_t)e0.x * 32 + lane]);
        acc.x += v0 * xa.x; acc.y += v0 * xa.y;
        acc.z += v0 * xa.z; acc.w += v0 * xa.w;
    }
    half2 p0 = __floats2half2_rn(acc.x, acc.y);
    half2 p1 = __floats2half2_rn(acc.z, acc.w);
    S[(size_t)row * 32 + lane] = make_uint2(*(uint32_t*)&p0, *(uint32_t*)&p1);
}

__global__ void spmm2_kernel() {
    int warp = (blockIdx.x * blockDim.x + threadIdx.x) >> 5;
    int lane = threadIdx.x & 31;
    if (warp < NN0)            spmm_row(g_h0, g_rp0, g_e0, g_S0h, warp, lane);
    else if (warp < NN0 + NN2) spmm_row(g_h1, g_rp2, g_e2, g_S2h, warp - NN0, lane);
}

// ---------------- persistent GEMM: resident W, A fragments via direct LDG, no in-loop syncs ----------------
#define PADH 136
#define T0 ((NN0 + 63) / 64)
#define T2 ((NN2 + 63) / 64)
#define PB0 198
#define PB2 98
#define PBT (PB0 + PB2)           // 296 = 2 per SM
#define GSMEM (2 * DD * PADH * 2) // bytes: 2 W planes only

__device__ __forceinline__ void mma_f16(float* d, const uint32_t* a, const uint32_t* b) {
    asm volatile(
        "mma.sync.aligned.m16n8k16.row.col.f32.f16.f16.f32 "
        "{%0,%1,%2,%3}, {%4,%5,%6,%7}, {%8,%9}, {%0,%1,%2,%3};\n"
        : "+f"(d[0]), "+f"(d[1]), "+f"(d[2]), "+f"(d[3])
        : "r"(a[0]), "r"(a[1]), "r"(a[2]), "r"(a[3]), "r"(b[0]), "r"(b[1]));
}

__global__ __launch_bounds__(256, 2)
void gemm2_f16_relu_kernel(float* __restrict__ out_y0, float* __restrict__ out_y2) {
    const uint2* Sh; const __half* WThi; const __half* WTlo; float* out; int M, T, first, stride;
    if (blockIdx.x < PB0) {
        Sh = g_S0h; WThi = g_WT0hi; WTlo = g_WT0lo; out = out_y0; M = NN0;
        T = T0; first = blockIdx.x; stride = PB0;
    } else {
        Sh = g_S2h; WThi = g_WT2hi; WTlo = g_WT2lo; out = out_y2; M = NN2;
        T = T2; first = blockIdx.x - PB0; stride = PB2;
    }

    extern __shared__ __half hsm[];
    __half* sWhi = hsm;                 // [128][PADH]
    __half* sWlo = hsm + DD * PADH;
    int tid = threadIdx.x;

    for (int idx = tid; idx < DD * 16; idx += 256) {
        int n = idx >> 4, kc = idx & 15;
        *(int4*)(sWhi + n * PADH + kc * 8) = ((const int4*)WThi)[idx];
        *(int4*)(sWlo + n * PADH + kc * 8) = ((const int4*)WTlo)[idx];
    }
    __syncthreads();   // only barrier in the kernel

    int lane = tid & 31, wid = tid >> 5;
    int g = lane >> 2, i4 = lane & 3;
    int mg = wid & 1, ng = wid >> 1;

    const uint32_t* GA  = (const uint32_t*)Sh;   // 64 words per row
    const uint32_t* sH32 = (const uint32_t*)sWhi;
    const uint32_t* sL32 = (const uint32_t*)sWlo;

    for (int t = first; t < T; t += stride) {
        int m0 = t * 64;
        int ra0 = m0 + mg * 32 + g;          // mt=0 rows: ra0, ra0+8
        int ra1 = ra0 + 16;                  // mt=1 rows: ra1, ra1+8
        size_t base00 = (size_t)ra0 * 64;
        size_t base01 = (size_t)(ra0 + 8) * 64;
        size_t base10 = (size_t)ra1 * 64;
        size_t base11 = (size_t)(ra1 + 8) * 64;
        bool p00 = ra0 < M, p01 = ra0 + 8 < M, p10 = ra1 < M, p11 = ra1 + 8 < M;

        float acc[2][4][4];
        #pragma unroll
        for (int mt = 0; mt < 2; mt++)
            #pragma unroll
            for (int nt = 0; nt < 4; nt++)
                #pragma unroll
                for (int q = 0; q < 4; q++) acc[mt][nt][q] = 0.f;

        #pragma unroll 2
        for (int kk = 0; kk < 8; kk++) {
            int kw = kk * 8 + i4;
            uint32_t a[2][4], bh[4][2], bl[4][2];
            a[0][0] = p00 ? GA[base00 + kw]     : 0u;
            a[0][1] = p01 ? GA[base01 + kw]     : 0u;
            a[0][2] = p00 ? GA[base00 + kw + 4] : 0u;
            a[0][3] = p01 ? GA[base01 + kw + 4] : 0u;
            a[1][0] = p10 ? GA[base10 + kw]     : 0u;
            a[1][1] = p11 ? GA[base11 + kw]     : 0u;
            a[1][2] = p10 ? GA[base10 + kw + 4] : 0u;
            a[1][3] = p11 ? GA[base11 + kw + 4] : 0u;
            #pragma unroll
            for (int nt = 0; nt < 4; nt++) {
                int n = (ng * 32 + nt * 8 + g) * (PADH / 2);
                bh[nt][0] = sH32[n + kw];
                bh[nt][1] = sH32[n + kw + 4];
                bl[nt][0] = sL32[n + kw];
                bl[nt][1] = sL32[n + kw + 4];
            }
            #pragma unroll
            for (int mt = 0; mt < 2; mt++)
                #pragma unroll
                for (int nt = 0; nt < 4; nt++) {
                    mma_f16(acc[mt][nt], a[mt], bl[nt]);
                    mma_f16(acc[mt][nt], a[mt], bh[nt]);
                }
        }

        #pragma unroll
        for (int mt = 0; mt < 2; mt++) {
            int r0 = m0 + mg * 32 + mt * 16 + g;
            #pragma unroll
            for (int nt = 0; nt < 4; nt++) {
                int c = ng * 32 + nt * 8 + i4 * 2;
                if (r0 < M) {
                    float2 v = make_float2(fmaxf(acc[mt][nt][0], 0.f),
                                           fmaxf(acc[mt][nt][1], 0.f));
                    *(float2*)(out + (size_t)r0 * DD + c) = v;
                }
                if (r0 + 8 < M) {
                    float2 v = make_float2(fmaxf(acc[mt][nt][2], 0.f),
                                           fmaxf(acc[mt][nt][3], 0.f));
                    *(float2*)(out + (size_t)(r0 + 8) * DD + c) = v;
                }
            }
        }
    }
}

// ---------------- tail: re-zero counters/flags/barriers ----------------
__global__ void tail_kernel() {
    int i = blockIdx.x * blockDim.x + threadIdx.x;
    if (i < NN0) g_fill0[i] = 0;
    else if (i < NN0 + NN2) g_fill2[i - NN0] = 0;
    else if (i < NN0 + NN2 + NBT) g_flagA[i - NN0 - NN2] = 0;
    else if (i == NN0 + NN2 + NBT)     g_bar1 = 0;
    else if (i == NN0 + NN2 + NBT + 1) g_bar2 = 0;
}

// ---------------- host launch ----------------
extern "C" void kernel_launch(void* const* d_in, const int* in_sizes, int n_in,
                              void* d_out, int out_size) {
    const float* x0  = (const float*)d_in[0];
    const float* x1  = (const float*)d_in[1];
    const int*   r00 = (const int*)  d_in[2];
    const int*   c00 = (const int*)  d_in[3];
    const float* v00 = (const float*)d_in[4];
    const int*   r12 = (const int*)  d_in[5];
    const int*   c12 = (const int*)  d_in[6];
    const float* v12 = (const float*)d_in[7];
    const float* W0  = (const float*)d_in[8];
    const float* W12 = (const float*)d_in[9];

    float* out    = (float*)d_out;
    float* out_y0 = out;
    float* out_x1 = out + (size_t)NN0 * DD;
    float* out_y2 = out + (size_t)(NN0 + NN1) * DD;

    front_kernel<<<NBT, 1024>>>(x0, x1, r00, r12, W0, W12, out_x1);        // #1
    fill2_kernel<<<(NNZ00 + NNZ12 + 255) / 256, 256>>>(r00, c00, v00,
                                                       r12, c12, v12);    // #2
    spmm2_kernel<<<((NN0 + NN2) * 32 + 255) / 256, 256>>>();               // #3
    cudaFuncSetAttribute(gemm2_f16_relu_kernel,
                         cudaFuncAttributeMaxDynamicSharedMemorySize, GSMEM);
    gemm2_f16_relu_kernel<<<PBT, 256, GSMEM>>>(out_y0, out_y2);            // #4 (profiled)
    tail_kernel<<<(NN0 + NN2 + NBT + 2 + 255) / 256, 256>>>();             // #5
}